// round 3
// baseline (speedup 1.0000x reference)
#include <cuda_runtime.h>
#include <cuda_fp16.h>
#include <cstdint>
#include <cstddef>

// ============================================================================
// QuaternionLinear == one dense GEMM: C[32768,1024] = X[32768,1024] @ W^T
//   W[4o+oc, 4i+ic] = S[oc][ic] * w_{T[oc][ic]}[o,i]
// compute_103 PTX target rejects tcgen05.* -> cp.async + ldmatrix + mma.sync.
// R3: CTA tile 128x256 (warp tile 64x64) to unbind SMEM crossbar from tensor
// pipe; fused prologue (W build + X fp32->fp16 convert) in one launch.
// ============================================================================

#define IN_F    1024
#define OUT_F   1024
#define M_TOTAL 32768

__device__ __half g_W[(size_t)OUT_F * IN_F];            // 2 MB
__device__ __half g_X[(size_t)M_TOTAL * IN_F];          // 64 MB scratch

__constant__ int   c_T[16] = {0,1,2,3,  1,0,3,2,  2,3,0,1,  3,2,1,0};
__constant__ float c_S[16] = {1,-1,-1,-1,  1,1,1,-1,  1,-1,1,1,  1,1,-1,1};

// --------------------------------------------------------------------------
// Fused prologue: blocks [0, 1024) build W; blocks [1024, 17408) convert X.
// --------------------------------------------------------------------------
constexpr int WBLOCKS = OUT_F * 256 / 256;                    // 1024
constexpr int XBLOCKS = (M_TOTAL * IN_F / 8) / 256;           // 16384 (8 floats/thr)

__global__ void prologue_kernel(const float* __restrict__ rw, const float* __restrict__ iw,
                                const float* __restrict__ jw, const float* __restrict__ kw,
                                const float* __restrict__ x) {
    if (blockIdx.x < WBLOCKS) {
        int idx = blockIdx.x * 256 + threadIdx.x;   // idx = n*256 + i
        int n = idx >> 8;
        int i = idx & 255;
        int o = n >> 2, oc = n & 3;
        const float* ws[4] = {rw, iw, jw, kw};
        float v0 = c_S[oc*4+0] * ws[c_T[oc*4+0]][o*256 + i];
        float v1 = c_S[oc*4+1] * ws[c_T[oc*4+1]][o*256 + i];
        float v2 = c_S[oc*4+2] * ws[c_T[oc*4+2]][o*256 + i];
        float v3 = c_S[oc*4+3] * ws[c_T[oc*4+3]][o*256 + i];
        __half2 h01 = __floats2half2_rn(v0, v1);
        __half2 h23 = __floats2half2_rn(v2, v3);
        uint2 p;
        p.x = *reinterpret_cast<uint32_t*>(&h01);
        p.y = *reinterpret_cast<uint32_t*>(&h23);
        *reinterpret_cast<uint2*>(&g_W[(size_t)n * IN_F + 4 * i]) = p;
    } else {
        size_t i = ((size_t)(blockIdx.x - WBLOCKS) * 256 + threadIdx.x) * 2;  // float4 idx
        #pragma unroll
        for (int j = 0; j < 2; j++) {
            float4 f = reinterpret_cast<const float4*>(x)[i + j];
            __half2 h0 = __floats2half2_rn(f.x, f.y);
            __half2 h1 = __floats2half2_rn(f.z, f.w);
            uint2 p;
            p.x = *reinterpret_cast<uint32_t*>(&h0);
            p.y = *reinterpret_cast<uint32_t*>(&h1);
            reinterpret_cast<uint2*>(g_X)[i + j] = p;
        }
    }
}

// --------------------------------------------------------------------------
// helpers
// --------------------------------------------------------------------------
__device__ __forceinline__ uint32_t smem_u32(const void* p) {
    uint32_t a;
    asm("{ .reg .u64 t; cvta.to.shared.u64 t, %1; cvt.u32.u64 %0, t; }" : "=r"(a) : "l"(p));
    return a;
}

__device__ __forceinline__ void cp_async16(uint32_t saddr, const void* gptr) {
    asm volatile("cp.async.cg.shared.global [%0], [%1], 16;" :: "r"(saddr), "l"(gptr));
}

#define CP_COMMIT() asm volatile("cp.async.commit_group;" ::: "memory")
#define CP_WAIT2()  asm volatile("cp.async.wait_group 2;" ::: "memory")

#define LDSM4(r, addr)                                                         \
    asm volatile("ldmatrix.sync.aligned.m8n8.x4.shared.b16 {%0,%1,%2,%3}, [%4];" \
                 : "=r"((r)[0]), "=r"((r)[1]), "=r"((r)[2]), "=r"((r)[3])       \
                 : "r"(addr))

#define MMA16816(c, a, b0, b1)                                                 \
    asm volatile("mma.sync.aligned.m16n8k16.row.col.f32.f16.f16.f32 "          \
                 "{%0,%1,%2,%3}, {%4,%5,%6,%7}, {%8,%9}, {%0,%1,%2,%3};"       \
                 : "+f"((c)[0]), "+f"((c)[1]), "+f"((c)[2]), "+f"((c)[3])      \
                 : "r"((a)[0]), "r"((a)[1]), "r"((a)[2]), "r"((a)[3]),         \
                   "r"(b0), "r"(b1))

__device__ __forceinline__ uint32_t swz(uint32_t off) {
    return off ^ ((off >> 3) & 0x70u);   // 128B-row XOR swizzle
}

// --------------------------------------------------------------------------
// GEMM config: CTA 128x256, warp tile 64x64, BK=64, 4 stages
// --------------------------------------------------------------------------
constexpr int BM = 128, BN = 256, BK = 64;
constexpr int NCHUNK = IN_F / BK;          // 16
constexpr int ASTG = BM * BK * 2;          // 16384 B
constexpr int BSTG = BN * BK * 2;          // 32768 B
constexpr int STAGES = 4;
constexpr int SM_B    = STAGES * ASTG;               // 65536
constexpr int SM_BIAS = SM_B + STAGES * BSTG;        // 196608
constexpr int SM_TOTAL = SM_BIAS + 1024;             // 197632

__global__ void __launch_bounds__(256, 1)
qgemm(const float* __restrict__ bias, float* __restrict__ out) {
    extern __shared__ __align__(1024) char smem[];
    const uint32_t sb = smem_u32(smem);
    const int tid  = threadIdx.x;
    const int lane = tid & 31;
    const int wid  = tid >> 5;
    const int warp_m = wid >> 2;            // 0..1  (64 rows)
    const int warp_n = wid & 3;             // 0..3  (64 cols)
    const int m_base = blockIdx.y * BM;
    const int n_base = blockIdx.x * BN;

    reinterpret_cast<float*>(smem + SM_BIAS)[tid] = bias[n_base + tid];

    // per-thread cp.async geometry: 16B segment per op, 128B rows
    const int seg  = tid & 7;               // 8 segs per row
    const int row0 = tid >> 3;              // 32 rows per round

    auto load_chunk = [&](int s, int c) {
        const int k0 = c * BK;
        const __half* ga = g_X + (size_t)m_base * IN_F + k0 + seg * 8;
        const __half* gb = g_W + (size_t)n_base * IN_F + k0 + seg * 8;
        const uint32_t sA = sb + s * ASTG;
        const uint32_t sB2 = sb + SM_B + s * BSTG;
        #pragma unroll
        for (int r = 0; r < 4; r++) {       // A: 128 rows
            int row = row0 + r * 32;
            uint32_t off = swz((uint32_t)row * 128u + (uint32_t)seg * 16u);
            cp_async16(sA + off, ga + (size_t)row * IN_F);
        }
        #pragma unroll
        for (int r = 0; r < 8; r++) {       // B: 256 rows
            int row = row0 + r * 32;
            uint32_t off = swz((uint32_t)row * 128u + (uint32_t)seg * 16u);
            cp_async16(sB2 + off, gb + (size_t)row * IN_F);
        }
    };

    float acc[4][8][4] = {};

    #pragma unroll
    for (int s = 0; s < 3; s++) { load_chunk(s, s); CP_COMMIT(); }

    #pragma unroll 1
    for (int c = 0; c < NCHUNK; c++) {
        CP_WAIT2();
        __syncthreads();
        if (c + 3 < NCHUNK) load_chunk((c + 3) & 3, c + 3);
        CP_COMMIT();

        const int s = c & 3;
        const uint32_t sA = sb + s * ASTG;
        const uint32_t sB2 = sb + SM_B + s * BSTG;

        #pragma unroll
        for (int ks = 0; ks < 4; ks++) {
            uint32_t a[4][4], b[4][4];
            #pragma unroll
            for (int mt = 0; mt < 4; mt++) {
                int row = warp_m * 64 + mt * 16 + (lane & 15);
                int col = ks * 16 + (lane >> 4) * 8;
                LDSM4(a[mt], sA + swz((uint32_t)row * 128u + (uint32_t)col * 2u));
            }
            #pragma unroll
            for (int nt = 0; nt < 4; nt++) {
                int row = warp_n * 64 + nt * 16 + (lane & 7) + ((lane >> 4) & 1) * 8;
                int col = ks * 16 + ((lane >> 3) & 1) * 8;
                LDSM4(b[nt], sB2 + swz((uint32_t)row * 128u + (uint32_t)col * 2u));
            }
            #pragma unroll
            for (int mt = 0; mt < 4; mt++) {
                #pragma unroll
                for (int no = 0; no < 8; no++) {
                    MMA16816(acc[mt][no], a[mt],
                             b[no >> 1][(no & 1) * 2], b[no >> 1][(no & 1) * 2 + 1]);
                }
            }
        }
    }

    // epilogue: direct float2 stores + bias
    const float* sbias = reinterpret_cast<const float*>(smem + SM_BIAS);
    #pragma unroll
    for (int mt = 0; mt < 4; mt++) {
        int r0 = m_base + warp_m * 64 + mt * 16 + (lane >> 2);
        #pragma unroll
        for (int no = 0; no < 8; no++) {
            int cl = warp_n * 64 + no * 8 + (lane & 3) * 2;   // local col
            float b0 = sbias[cl], b1 = sbias[cl + 1];
            float2 v0 = make_float2(acc[mt][no][0] + b0, acc[mt][no][1] + b1);
            float2 v1 = make_float2(acc[mt][no][2] + b0, acc[mt][no][3] + b1);
            *reinterpret_cast<float2*>(out + (size_t)r0 * OUT_F + n_base + cl)       = v0;
            *reinterpret_cast<float2*>(out + (size_t)(r0 + 8) * OUT_F + n_base + cl) = v1;
        }
    }
}

// --------------------------------------------------------------------------
extern "C" void kernel_launch(void* const* d_in, const int* in_sizes, int n_in,
                              void* d_out, int out_size) {
    const float* x    = (const float*)d_in[0];
    const float* rw   = (const float*)d_in[1];
    const float* iw   = (const float*)d_in[2];
    const float* jw   = (const float*)d_in[3];
    const float* kw   = (const float*)d_in[4];
    const float* bias = (const float*)d_in[5];
    float* out = (float*)d_out;

    static bool attr_done = false;
    if (!attr_done) {
        cudaFuncSetAttribute(qgemm, cudaFuncAttributeMaxDynamicSharedMemorySize, SM_TOTAL);
        attr_done = true;
    }

    prologue_kernel<<<WBLOCKS + XBLOCKS, 256>>>(rw, iw, jw, kw, x);

    dim3 grid(OUT_F / BN, M_TOTAL / BM);   // (4, 256): N fastest -> A-tile L2 reuse
    qgemm<<<grid, 256, SM_TOTAL>>>(bias, out);
}

// round 4
// speedup vs baseline: 1.6828x; 1.6828x over previous
#include <cuda_runtime.h>
#include <cuda_fp16.h>
#include <cstdint>
#include <cstddef>

// ============================================================================
// QuaternionLinear == one dense GEMM: C[32768,1024] = X[32768,1024] @ W^T
//   W[4o+oc, 4i+ic] = S[oc][ic] * w_{T[oc][ic]}[o,i]
// compute_103 PTX target rejects tcgen05.* -> cp.async + ldmatrix + mma.sync.
// R4: back to CTA 128x128 / warp 64x32 (R2 geometry), 3 stages -> 2 CTAs/SM
// (occupancy was the R3 killer: 242 regs, 2 warps/SMSP). Fused prologue.
// ============================================================================

#define IN_F    1024
#define OUT_F   1024
#define M_TOTAL 32768

__device__ __half g_W[(size_t)OUT_F * IN_F];            // 2 MB
__device__ __half g_X[(size_t)M_TOTAL * IN_F];          // 64 MB scratch

__constant__ int   c_T[16] = {0,1,2,3,  1,0,3,2,  2,3,0,1,  3,2,1,0};
__constant__ float c_S[16] = {1,-1,-1,-1,  1,1,1,-1,  1,-1,1,1,  1,1,-1,1};

// --------------------------------------------------------------------------
// Fused prologue: blocks [0, 1024) build W; blocks [1024, 17408) convert X.
// --------------------------------------------------------------------------
constexpr int WBLOCKS = OUT_F * 256 / 256;                    // 1024
constexpr int XBLOCKS = (M_TOTAL * IN_F / 8) / 256;           // 16384

__global__ void prologue_kernel(const float* __restrict__ rw, const float* __restrict__ iw,
                                const float* __restrict__ jw, const float* __restrict__ kw,
                                const float* __restrict__ x) {
    if (blockIdx.x < WBLOCKS) {
        int idx = blockIdx.x * 256 + threadIdx.x;   // idx = n*256 + i
        int n = idx >> 8;
        int i = idx & 255;
        int o = n >> 2, oc = n & 3;
        const float* ws[4] = {rw, iw, jw, kw};
        float v0 = c_S[oc*4+0] * ws[c_T[oc*4+0]][o*256 + i];
        float v1 = c_S[oc*4+1] * ws[c_T[oc*4+1]][o*256 + i];
        float v2 = c_S[oc*4+2] * ws[c_T[oc*4+2]][o*256 + i];
        float v3 = c_S[oc*4+3] * ws[c_T[oc*4+3]][o*256 + i];
        __half2 h01 = __floats2half2_rn(v0, v1);
        __half2 h23 = __floats2half2_rn(v2, v3);
        uint2 p;
        p.x = *reinterpret_cast<uint32_t*>(&h01);
        p.y = *reinterpret_cast<uint32_t*>(&h23);
        *reinterpret_cast<uint2*>(&g_W[(size_t)n * IN_F + 4 * i]) = p;
    } else {
        size_t i = ((size_t)(blockIdx.x - WBLOCKS) * 256 + threadIdx.x) * 2;  // float4 idx
        #pragma unroll
        for (int j = 0; j < 2; j++) {
            float4 f = reinterpret_cast<const float4*>(x)[i + j];
            __half2 h0 = __floats2half2_rn(f.x, f.y);
            __half2 h1 = __floats2half2_rn(f.z, f.w);
            uint2 p;
            p.x = *reinterpret_cast<uint32_t*>(&h0);
            p.y = *reinterpret_cast<uint32_t*>(&h1);
            reinterpret_cast<uint2*>(g_X)[i + j] = p;
        }
    }
}

// --------------------------------------------------------------------------
// helpers
// --------------------------------------------------------------------------
__device__ __forceinline__ uint32_t smem_u32(const void* p) {
    uint32_t a;
    asm("{ .reg .u64 t; cvta.to.shared.u64 t, %1; cvt.u32.u64 %0, t; }" : "=r"(a) : "l"(p));
    return a;
}

__device__ __forceinline__ void cp_async16(uint32_t saddr, const void* gptr) {
    asm volatile("cp.async.cg.shared.global [%0], [%1], 16;" :: "r"(saddr), "l"(gptr));
}

#define CP_COMMIT() asm volatile("cp.async.commit_group;" ::: "memory")
#define CP_WAIT1()  asm volatile("cp.async.wait_group 1;" ::: "memory")

#define LDSM4(r, addr)                                                         \
    asm volatile("ldmatrix.sync.aligned.m8n8.x4.shared.b16 {%0,%1,%2,%3}, [%4];" \
                 : "=r"((r)[0]), "=r"((r)[1]), "=r"((r)[2]), "=r"((r)[3])       \
                 : "r"(addr))

#define MMA16816(c, a, b0, b1)                                                 \
    asm volatile("mma.sync.aligned.m16n8k16.row.col.f32.f16.f16.f32 "          \
                 "{%0,%1,%2,%3}, {%4,%5,%6,%7}, {%8,%9}, {%0,%1,%2,%3};"       \
                 : "+f"((c)[0]), "+f"((c)[1]), "+f"((c)[2]), "+f"((c)[3])      \
                 : "r"((a)[0]), "r"((a)[1]), "r"((a)[2]), "r"((a)[3]),         \
                   "r"(b0), "r"(b1))

__device__ __forceinline__ uint32_t swz(uint32_t off) {
    return off ^ ((off >> 3) & 0x70u);   // 128B-row XOR swizzle
}

// --------------------------------------------------------------------------
// GEMM config: CTA 128x128, warp tile 64x32, BK=64, 3 stages, 2 CTAs/SM
// --------------------------------------------------------------------------
constexpr int BM = 128, BN = 128, BK = 64;
constexpr int NCHUNK = IN_F / BK;          // 16
constexpr int ASTG = BM * BK * 2;          // 16384 B
constexpr int BSTG = BN * BK * 2;          // 16384 B
constexpr int STAGES = 3;
constexpr int SM_B    = STAGES * ASTG;               // 49152
constexpr int SM_BIAS = SM_B + STAGES * BSTG;        // 98304
constexpr int SM_TOTAL = SM_BIAS + 512;              // 98816 -> 2 CTAs/SM

__global__ void __launch_bounds__(256, 2)
qgemm(const float* __restrict__ bias, float* __restrict__ out) {
    extern __shared__ __align__(1024) char smem[];
    const uint32_t sb = smem_u32(smem);
    const int tid  = threadIdx.x;
    const int lane = tid & 31;
    const int wid  = tid >> 5;
    const int warp_m = wid >> 2;            // 0..1  (64 rows each)
    const int warp_n = wid & 3;             // 0..3  (32 cols each)
    const int m_base = blockIdx.y * BM;
    const int n_base = blockIdx.x * BN;

    if (tid < 128) reinterpret_cast<float*>(smem + SM_BIAS)[tid] = bias[n_base + tid];

    // per-thread cp.async geometry: 16B segment per op, 128B rows
    const int seg  = tid & 7;               // 8 segs per 128B row
    const int row0 = tid >> 3;              // 32 rows per round

    auto load_chunk = [&](int s, int c) {
        const int k0 = c * BK;
        const __half* ga = g_X + (size_t)m_base * IN_F + k0 + seg * 8;
        const __half* gb = g_W + (size_t)n_base * IN_F + k0 + seg * 8;
        const uint32_t sA  = sb + s * ASTG;
        const uint32_t sB2 = sb + SM_B + s * BSTG;
        #pragma unroll
        for (int r = 0; r < 4; r++) {
            int row = row0 + r * 32;
            uint32_t off = swz((uint32_t)row * 128u + (uint32_t)seg * 16u);
            cp_async16(sA  + off, ga + (size_t)row * IN_F);
            cp_async16(sB2 + off, gb + (size_t)row * IN_F);
        }
    };

    float acc[4][4][4] = {};

    #pragma unroll
    for (int s = 0; s < 2; s++) { load_chunk(s, s); CP_COMMIT(); }

    #pragma unroll 1
    for (int c = 0; c < NCHUNK; c++) {
        CP_WAIT1();
        __syncthreads();
        if (c + 2 < NCHUNK) load_chunk((c + 2) % 3, c + 2);
        CP_COMMIT();

        const int s = c % 3;
        const uint32_t sA  = sb + s * ASTG;
        const uint32_t sB2 = sb + SM_B + s * BSTG;

        #pragma unroll
        for (int ks = 0; ks < 4; ks++) {
            uint32_t a[4][4], b[2][4];
            #pragma unroll
            for (int mt = 0; mt < 4; mt++) {
                int row = warp_m * 64 + mt * 16 + (lane & 15);
                int col = ks * 16 + (lane >> 4) * 8;
                LDSM4(a[mt], sA + swz((uint32_t)row * 128u + (uint32_t)col * 2u));
            }
            #pragma unroll
            for (int nt = 0; nt < 2; nt++) {
                int row = warp_n * 32 + nt * 16 + (lane & 7) + ((lane >> 4) & 1) * 8;
                int col = ks * 16 + ((lane >> 3) & 1) * 8;
                LDSM4(b[nt], sB2 + swz((uint32_t)row * 128u + (uint32_t)col * 2u));
            }
            #pragma unroll
            for (int mt = 0; mt < 4; mt++) {
                #pragma unroll
                for (int no = 0; no < 4; no++) {
                    MMA16816(acc[mt][no], a[mt],
                             b[no >> 1][(no & 1) * 2], b[no >> 1][(no & 1) * 2 + 1]);
                }
            }
        }
    }

    // epilogue: direct float2 stores + bias
    const float* sbias = reinterpret_cast<const float*>(smem + SM_BIAS);
    #pragma unroll
    for (int mt = 0; mt < 4; mt++) {
        int r0 = m_base + warp_m * 64 + mt * 16 + (lane >> 2);
        #pragma unroll
        for (int no = 0; no < 4; no++) {
            int cl = warp_n * 32 + no * 8 + (lane & 3) * 2;   // local col
            float b0 = sbias[cl], b1 = sbias[cl + 1];
            float2 v0 = make_float2(acc[mt][no][0] + b0, acc[mt][no][1] + b1);
            float2 v1 = make_float2(acc[mt][no][2] + b0, acc[mt][no][3] + b1);
            *reinterpret_cast<float2*>(out + (size_t)r0 * OUT_F + n_base + cl)       = v0;
            *reinterpret_cast<float2*>(out + (size_t)(r0 + 8) * OUT_F + n_base + cl) = v1;
        }
    }
}

// --------------------------------------------------------------------------
extern "C" void kernel_launch(void* const* d_in, const int* in_sizes, int n_in,
                              void* d_out, int out_size) {
    const float* x    = (const float*)d_in[0];
    const float* rw   = (const float*)d_in[1];
    const float* iw   = (const float*)d_in[2];
    const float* jw   = (const float*)d_in[3];
    const float* kw   = (const float*)d_in[4];
    const float* bias = (const float*)d_in[5];
    float* out = (float*)d_out;

    static bool attr_done = false;
    if (!attr_done) {
        cudaFuncSetAttribute(qgemm, cudaFuncAttributeMaxDynamicSharedMemorySize, SM_TOTAL);
        attr_done = true;
    }

    prologue_kernel<<<WBLOCKS + XBLOCKS, 256>>>(rw, iw, jw, kw, x);

    dim3 grid(OUT_F / BN, M_TOTAL / BM);   // (8, 256): N fastest -> A-tile L2 reuse
    qgemm<<<grid, 256, SM_TOTAL>>>(bias, out);
}